// round 15
// baseline (speedup 1.0000x reference)
#include <cuda_runtime.h>
#include <cuda_bf16.h>
#include <cstdint>

// ===================== problem constants =====================
static constexpr int MROWS = 32768;
static constexpr int KDIM  = 1024;
static constexpr int NDIM  = 1024;

// ===================== HMMA GEMM tiling =====================
static constexpr int BM = 128;
static constexpr int BN = 256;
static constexpr int BK = 64;                 // bf16 k per tile (128 bytes)
static constexpr int KTILES = KDIM / BK;      // 16
static constexpr int NSTAGE = 3;
static constexpr int ROWB = 128;              // bytes per smem row (swizzled)
static constexpr int A_TILE = BM * ROWB;                // 16KB
static constexpr int B_TILE = BN * ROWB;                // 32KB
static constexpr int STAGE_BYTES = A_TILE + B_TILE;     // 48KB
static constexpr int SMEM_BYTES = NSTAGE * STAGE_BYTES; // 147456

// ===================== scratch =====================
__device__ __align__(16) __nv_bfloat16 g_qh[(size_t)MROWS * KDIM];   // bf16 acts (64MB)
__device__ __align__(16) __nv_bfloat16 g_wh[(size_t)NDIM * KDIM];    // bf16 weights (2MB)

// ===================== helpers =====================
__device__ __forceinline__ uint32_t smem_u32(const void* p) {
    uint32_t a;
    asm("{ .reg .u64 t; cvta.to.shared.u64 t, %1; cvt.u32.u64 %0, t; }" : "=r"(a) : "l"(p));
    return a;
}
__device__ __forceinline__ void cp_async16(uint32_t dst, const void* src) {
    asm volatile("cp.async.cg.shared.global [%0], [%1], 16;" :: "r"(dst), "l"(src) : "memory");
}
__device__ __forceinline__ void cp_commit() {
    asm volatile("cp.async.commit_group;" ::: "memory");
}
template <int N>
__device__ __forceinline__ void cp_wait() {
    asm volatile("cp.async.wait_group %0;" :: "n"(N) : "memory");
}
__device__ __forceinline__ void ldsm_x4(uint32_t* r, uint32_t addr) {
    asm volatile("ldmatrix.sync.aligned.m8n8.x4.shared.b16 {%0,%1,%2,%3}, [%4];"
                 : "=r"(r[0]), "=r"(r[1]), "=r"(r[2]), "=r"(r[3]) : "r"(addr));
}
__device__ __forceinline__ void mma_bf16(float* d, const uint32_t* a, const uint32_t* b) {
    asm volatile(
        "mma.sync.aligned.m16n8k16.row.col.f32.bf16.bf16.f32 "
        "{%0,%1,%2,%3}, {%4,%5,%6,%7}, {%8,%9}, {%0,%1,%2,%3};"
        : "+f"(d[0]), "+f"(d[1]), "+f"(d[2]), "+f"(d[3])
        : "r"(a[0]), "r"(a[1]), "r"(a[2]), "r"(a[3]), "r"(b[0]), "r"(b[1]));
}

// ===================== pass 1: quantize fp32 -> bf16 ints =====================
__global__ void __launch_bounds__(256) quant_kernel(const float* __restrict__ x) {
    const int i = blockIdx.x * blockDim.x + threadIdx.x;   // one 16-element group
    const int ngroups = (MROWS * KDIM) / 16;
    if (i >= ngroups) return;
    const float4* xv = (const float4*)x + i * 4;
    uint32_t hb[8];
#pragma unroll
    for (int j = 0; j < 4; j++) {
        float4 v = xv[j];
        int q0 = max(-127, min(127, __float2int_rn(__fmul_rn(v.x, 20.0f))));
        int q1 = max(-127, min(127, __float2int_rn(__fmul_rn(v.y, 20.0f))));
        int q2 = max(-127, min(127, __float2int_rn(__fmul_rn(v.z, 20.0f))));
        int q3 = max(-127, min(127, __float2int_rn(__fmul_rn(v.w, 20.0f))));
        __nv_bfloat162 p01 = __floats2bfloat162_rn((float)q0, (float)q1);
        __nv_bfloat162 p23 = __floats2bfloat162_rn((float)q2, (float)q3);
        hb[2 * j]     = *(uint32_t*)&p01;
        hb[2 * j + 1] = *(uint32_t*)&p23;
    }
    uint4 h0; h0.x = hb[0]; h0.y = hb[1]; h0.z = hb[2]; h0.w = hb[3];
    uint4 h1; h1.x = hb[4]; h1.y = hb[5]; h1.z = hb[6]; h1.w = hb[7];
    ((uint4*)g_qh)[i * 2]     = h0;
    ((uint4*)g_qh)[i * 2 + 1] = h1;
}

// ===================== pass 1b: unpack int4 -> bf16 =====================
// weight_packed delivered as int32 elements (uint8 widened by harness).
__global__ void __launch_bounds__(256) unpack_kernel(const int4* __restrict__ wp) {
    int i = blockIdx.x * blockDim.x + threadIdx.x;   // one int4 = 4 packed bytes = 8 weights
    if (i >= (NDIM * KDIM) / 8) return;
    int4 e = wp[i];
    int b[4] = {e.x & 0xFF, e.y & 0xFF, e.z & 0xFF, e.w & 0xFF};
    uint4 h;
    uint32_t* hw = (uint32_t*)&h;
#pragma unroll
    for (int j = 0; j < 4; j++) {
        int lo = (b[j] & 0xF);        lo -= (lo >= 8) ? 16 : 0;
        int hi = (b[j] >> 4) & 0xF;   hi -= (hi >= 8) ? 16 : 0;
        __nv_bfloat162 p = __floats2bfloat162_rn((float)lo, (float)hi);
        hw[j] = *(uint32_t*)&p;
    }
    ((uint4*)g_wh)[i] = h;
}

// ===================== pass 2: HMMA bf16 GEMM =====================
// CTA: 256 threads = 8 warps in 2(m) x 4(n); warp tile 64x64 (mi=4, ni=8).
__global__ void __launch_bounds__(256, 1)
gemm_hmma(const float* __restrict__ bias, float* __restrict__ out) {
    extern __shared__ char smem[];
    const uint32_t sbase = smem_u32(smem);
    const int tid  = threadIdx.x;
    const int wid  = tid >> 5;
    const int lane = tid & 31;
    const int g = lane >> 2, t = lane & 3;
    const int wm = (wid & 1) * 64;
    const int wn = (wid >> 1) * 64;
    const int n0 = blockIdx.x * BN;
    const int m0 = blockIdx.y * BM;

    const __nv_bfloat16* gA = g_qh + (size_t)m0 * KDIM;
    const __nv_bfloat16* gB = g_wh + (size_t)n0 * KDIM;

    // swizzled store: row r, 16B-chunk c -> offset r*128 + (c ^ (r&7))*16
    auto load_stage = [&](int s, int kt) {
        const uint32_t sa = sbase + s * STAGE_BYTES;
        const uint32_t sb = sa + A_TILE;
        const int kb = kt * BK;       // bf16 elements
#pragma unroll
        for (int it = 0; it < 4; it++) {
            int c = tid + it * 256;           // 1024 chunks for A (128 rows x 8)
            int row = c >> 3, col = c & 7;
            int scol = col ^ (row & 7);
            cp_async16(sa + row * ROWB + scol * 16,
                       gA + (size_t)row * KDIM + kb + col * 8);
        }
#pragma unroll
        for (int it = 0; it < 8; it++) {
            int c = tid + it * 256;           // 2048 chunks for B (256 rows x 8)
            int row = c >> 3, col = c & 7;
            int scol = col ^ (row & 7);
            cp_async16(sb + row * ROWB + scol * 16,
                       gB + (size_t)row * KDIM + kb + col * 8);
        }
    };

    float acc[4][8][4];
#pragma unroll
    for (int mi = 0; mi < 4; mi++)
#pragma unroll
        for (int ni = 0; ni < 8; ni++)
#pragma unroll
            for (int r = 0; r < 4; r++) acc[mi][ni][r] = 0.0f;

    const int a_row   = wm + (lane & 15);
    const int a_chunk = lane >> 4;                              // 0 or 1
    const int b_row   = wn + (lane & 7) + ((lane >> 4) << 3);
    const int b_chunk = (lane >> 3) & 1;                        // 0 or 1

    // prologue: stages 0 and 1 (one commit group each)
    load_stage(0, 0); cp_commit();
    load_stage(1, 1); cp_commit();

#pragma unroll 1
    for (int kt = 0; kt < KTILES; kt++) {
        cp_wait<1>();        // stage kt's group complete (exactly 1 newer group)
        __syncthreads();     // arrival visible to all + stage (kt-1) reads done
        if (kt + 2 < KTILES) load_stage((kt + 2) % NSTAGE, kt + 2);
        cp_commit();         // unconditional: keeps group algebra uniform

        const uint32_t sa = sbase + (kt % NSTAGE) * STAGE_BYTES;
        const uint32_t sb = sa + A_TILE;

#pragma unroll
        for (int c = 0; c < 4; c++) {                 // four k16 chunks per ktile
            uint32_t afr[4][4];
#pragma unroll
            for (int mi = 0; mi < 4; mi++) {
                int r = a_row + mi * 16;
                int ch = (2 * c + a_chunk) ^ (r & 7);
                ldsm_x4(afr[mi], sa + r * ROWB + ch * 16);
            }
            uint32_t bfr[8][2];
#pragma unroll
            for (int p = 0; p < 4; p++) {
                int r = b_row + p * 16;
                int ch = (2 * c + b_chunk) ^ (r & 7);
                uint32_t r4[4];
                ldsm_x4(r4, sb + r * ROWB + ch * 16);
                bfr[2 * p][0] = r4[0]; bfr[2 * p][1] = r4[1];
                bfr[2 * p + 1][0] = r4[2]; bfr[2 * p + 1][1] = r4[3];
            }
#pragma unroll
            for (int mi = 0; mi < 4; mi++)
#pragma unroll
                for (int ni = 0; ni < 8; ni++)
                    mma_bf16(acc[mi][ni], afr[mi], bfr[ni]);
        }
    }

    // ---- epilogue: out = acc * (A_SCALE*W_SCALE) + bias, FP32 ----
    const float SCALE = 5.0e-4f;
#pragma unroll
    for (int mi = 0; mi < 4; mi++) {
        const int row = m0 + wm + mi * 16 + g;
        float* p0 = out + (size_t)row * NDIM + n0 + wn;
        float* p1 = p0 + (size_t)8 * NDIM;
#pragma unroll
        for (int ni = 0; ni < 8; ni++) {
            const float* cc = acc[mi][ni];
            const int coff = ni * 8 + t * 2;
            float b0 = bias[n0 + wn + coff];
            float b1 = bias[n0 + wn + coff + 1];
            float2 v01, v23;
            v01.x = __fadd_rn(__fmul_rn(cc[0], SCALE), b0);
            v01.y = __fadd_rn(__fmul_rn(cc[1], SCALE), b1);
            v23.x = __fadd_rn(__fmul_rn(cc[2], SCALE), b0);
            v23.y = __fadd_rn(__fmul_rn(cc[3], SCALE), b1);
            *(float2*)(p0 + coff) = v01;
            *(float2*)(p1 + coff) = v23;
        }
    }
}

// ===================== launch =====================
extern "C" void kernel_launch(void* const* d_in, const int* in_sizes, int n_in,
                              void* d_out, int out_size) {
    const float* x    = nullptr;
    const int*   wp   = nullptr;
    const float* bias = nullptr;
    for (int i = 0; i < n_in; i++) {
        if (in_sizes[i] == MROWS * KDIM)            x    = (const float*)d_in[i];
        else if (in_sizes[i] == NDIM * KDIM / 2)    wp   = (const int*)d_in[i];
        else if (in_sizes[i] == NDIM)               bias = (const float*)d_in[i];
    }
    if (x == nullptr)    x    = (const float*)d_in[0];
    if (wp == nullptr)   wp   = (const int*)d_in[1];
    if (bias == nullptr) bias = (const float*)d_in[2];
    float* out = (float*)d_out;

    quant_kernel<<<(MROWS * KDIM / 16 + 255) / 256, 256>>>(x);
    unpack_kernel<<<(NDIM * KDIM / 8 + 255) / 256, 256>>>((const int4*)wp);

    cudaFuncSetAttribute(gemm_hmma, cudaFuncAttributeMaxDynamicSharedMemorySize, SMEM_BYTES);
    dim3 grid(NDIM / BN, MROWS / BM);   // (4, 256)
    gemm_hmma<<<grid, 256, SMEM_BYTES>>>(bias, out);
}

// round 16
// speedup vs baseline: 1.0993x; 1.0993x over previous
#include <cuda_runtime.h>
#include <cuda_bf16.h>
#include <cstdint>

// ===================== problem constants =====================
static constexpr int MROWS = 32768;
static constexpr int KDIM  = 1024;
static constexpr int NDIM  = 1024;

// ===================== HMMA GEMM tiling =====================
static constexpr int BM = 128;
static constexpr int BN = 128;
static constexpr int BK = 64;                 // bf16 k per tile (128 bytes)
static constexpr int KTILES = KDIM / BK;      // 16
static constexpr int NSTAGE = 3;
static constexpr int ROWB = 128;              // bytes per smem row (swizzled)
static constexpr int A_TILE = BM * ROWB;                // 16KB
static constexpr int B_TILE = BN * ROWB;                // 16KB
static constexpr int STAGE_BYTES = A_TILE + B_TILE;     // 32KB
static constexpr int SMEM_BYTES = NSTAGE * STAGE_BYTES; // 98304

// ===================== scratch =====================
__device__ __align__(16) __nv_bfloat16 g_qh[(size_t)MROWS * KDIM];   // bf16 acts (64MB)
__device__ __align__(16) __nv_bfloat16 g_wh[(size_t)NDIM * KDIM];    // bf16 weights (2MB)

// ===================== helpers =====================
__device__ __forceinline__ uint32_t smem_u32(const void* p) {
    uint32_t a;
    asm("{ .reg .u64 t; cvta.to.shared.u64 t, %1; cvt.u32.u64 %0, t; }" : "=r"(a) : "l"(p));
    return a;
}
__device__ __forceinline__ void cp_async16(uint32_t dst, const void* src) {
    asm volatile("cp.async.cg.shared.global [%0], [%1], 16;" :: "r"(dst), "l"(src) : "memory");
}
__device__ __forceinline__ void cp_commit() {
    asm volatile("cp.async.commit_group;" ::: "memory");
}
template <int N>
__device__ __forceinline__ void cp_wait() {
    asm volatile("cp.async.wait_group %0;" :: "n"(N) : "memory");
}
__device__ __forceinline__ void ldsm_x4(uint32_t* r, uint32_t addr) {
    asm volatile("ldmatrix.sync.aligned.m8n8.x4.shared.b16 {%0,%1,%2,%3}, [%4];"
                 : "=r"(r[0]), "=r"(r[1]), "=r"(r[2]), "=r"(r[3]) : "r"(addr));
}
__device__ __forceinline__ void mma_bf16(float* d, const uint32_t* a, const uint32_t* b) {
    asm volatile(
        "mma.sync.aligned.m16n8k16.row.col.f32.bf16.bf16.f32 "
        "{%0,%1,%2,%3}, {%4,%5,%6,%7}, {%8,%9}, {%0,%1,%2,%3};"
        : "+f"(d[0]), "+f"(d[1]), "+f"(d[2]), "+f"(d[3])
        : "r"(a[0]), "r"(a[1]), "r"(a[2]), "r"(a[3]), "r"(b[0]), "r"(b[1]));
}

// ===================== pass 1: quantize fp32 -> bf16 ints =====================
__global__ void __launch_bounds__(256) quant_kernel(const float* __restrict__ x) {
    const int i = blockIdx.x * blockDim.x + threadIdx.x;   // one 16-element group
    const int ngroups = (MROWS * KDIM) / 16;
    if (i >= ngroups) return;
    const float4* xv = (const float4*)x + i * 4;
    uint32_t hb[8];
#pragma unroll
    for (int j = 0; j < 4; j++) {
        float4 v = xv[j];
        int q0 = max(-127, min(127, __float2int_rn(__fmul_rn(v.x, 20.0f))));
        int q1 = max(-127, min(127, __float2int_rn(__fmul_rn(v.y, 20.0f))));
        int q2 = max(-127, min(127, __float2int_rn(__fmul_rn(v.z, 20.0f))));
        int q3 = max(-127, min(127, __float2int_rn(__fmul_rn(v.w, 20.0f))));
        __nv_bfloat162 p01 = __floats2bfloat162_rn((float)q0, (float)q1);
        __nv_bfloat162 p23 = __floats2bfloat162_rn((float)q2, (float)q3);
        hb[2 * j]     = *(uint32_t*)&p01;
        hb[2 * j + 1] = *(uint32_t*)&p23;
    }
    uint4 h0; h0.x = hb[0]; h0.y = hb[1]; h0.z = hb[2]; h0.w = hb[3];
    uint4 h1; h1.x = hb[4]; h1.y = hb[5]; h1.z = hb[6]; h1.w = hb[7];
    ((uint4*)g_qh)[i * 2]     = h0;
    ((uint4*)g_qh)[i * 2 + 1] = h1;
}

// ===================== pass 1b: unpack int4 -> bf16 =====================
// weight_packed delivered as int32 elements (uint8 widened by harness).
__global__ void __launch_bounds__(256) unpack_kernel(const int4* __restrict__ wp) {
    int i = blockIdx.x * blockDim.x + threadIdx.x;   // one int4 = 4 packed bytes = 8 weights
    if (i >= (NDIM * KDIM) / 8) return;
    int4 e = wp[i];
    int b[4] = {e.x & 0xFF, e.y & 0xFF, e.z & 0xFF, e.w & 0xFF};
    uint4 h;
    uint32_t* hw = (uint32_t*)&h;
#pragma unroll
    for (int j = 0; j < 4; j++) {
        int lo = (b[j] & 0xF);        lo -= (lo >= 8) ? 16 : 0;
        int hi = (b[j] >> 4) & 0xF;   hi -= (hi >= 8) ? 16 : 0;
        __nv_bfloat162 p = __floats2bfloat162_rn((float)lo, (float)hi);
        hw[j] = *(uint32_t*)&p;
    }
    ((uint4*)g_wh)[i] = h;
}

// ===================== pass 2: HMMA bf16 GEMM =====================
// CTA: 128 threads = 4 warps in 2(m) x 2(n); warp tile 64x64 (mi=4, ni=8).
__global__ void __launch_bounds__(128, 2)
gemm_hmma(const float* __restrict__ bias, float* __restrict__ out) {
    extern __shared__ char smem[];
    const uint32_t sbase = smem_u32(smem);
    const int tid  = threadIdx.x;
    const int wid  = tid >> 5;
    const int lane = tid & 31;
    const int g = lane >> 2, t = lane & 3;
    const int wm = (wid & 1) * 64;
    const int wn = (wid >> 1) * 64;
    const int n0 = blockIdx.x * BN;
    const int m0 = blockIdx.y * BM;

    const __nv_bfloat16* gA = g_qh + (size_t)m0 * KDIM;
    const __nv_bfloat16* gB = g_wh + (size_t)n0 * KDIM;

    // swizzled store: row r, 16B-chunk c -> offset r*128 + (c ^ (r&7))*16
    auto load_stage = [&](int s, int kt) {
        const uint32_t sa = sbase + s * STAGE_BYTES;
        const uint32_t sb = sa + A_TILE;
        const int kb = kt * BK;       // bf16 elements
#pragma unroll
        for (int it = 0; it < 8; it++) {
            int c = tid + it * 128;           // 1024 chunks for A (128 rows x 8)
            int row = c >> 3, col = c & 7;
            int scol = col ^ (row & 7);
            cp_async16(sa + row * ROWB + scol * 16,
                       gA + (size_t)row * KDIM + kb + col * 8);
        }
#pragma unroll
        for (int it = 0; it < 8; it++) {
            int c = tid + it * 128;           // 1024 chunks for B (128 rows x 8)
            int row = c >> 3, col = c & 7;
            int scol = col ^ (row & 7);
            cp_async16(sb + row * ROWB + scol * 16,
                       gB + (size_t)row * KDIM + kb + col * 8);
        }
    };

    float acc[4][8][4];
#pragma unroll
    for (int mi = 0; mi < 4; mi++)
#pragma unroll
        for (int ni = 0; ni < 8; ni++)
#pragma unroll
            for (int r = 0; r < 4; r++) acc[mi][ni][r] = 0.0f;

    const int a_row   = wm + (lane & 15);
    const int a_chunk = lane >> 4;                              // 0 or 1
    const int b_row   = wn + (lane & 7) + ((lane >> 4) << 3);
    const int b_chunk = (lane >> 3) & 1;                        // 0 or 1

    // prologue: stages 0 and 1 (one commit group each)
    load_stage(0, 0); cp_commit();
    load_stage(1, 1); cp_commit();

#pragma unroll 1
    for (int kt = 0; kt < KTILES; kt++) {
        cp_wait<1>();        // stage kt's group complete (exactly 1 newer group)
        __syncthreads();     // arrival visible + stage (kt-1) reads done before overwrite
        if (kt + 2 < KTILES) load_stage((kt + 2) % NSTAGE, kt + 2);
        cp_commit();         // unconditional: keeps group algebra uniform

        const uint32_t sa = sbase + (kt % NSTAGE) * STAGE_BYTES;
        const uint32_t sb = sa + A_TILE;

#pragma unroll
        for (int c = 0; c < 4; c++) {                 // four k16 chunks per ktile
            uint32_t afr[4][4];
#pragma unroll
            for (int mi = 0; mi < 4; mi++) {
                int r = a_row + mi * 16;
                int ch = (2 * c + a_chunk) ^ (r & 7);
                ldsm_x4(afr[mi], sa + r * ROWB + ch * 16);
            }
            uint32_t bfr[8][2];
#pragma unroll
            for (int p = 0; p < 4; p++) {
                int r = b_row + p * 16;
                int ch = (2 * c + b_chunk) ^ (r & 7);
                uint32_t r4[4];
                ldsm_x4(r4, sb + r * ROWB + ch * 16);
                bfr[2 * p][0] = r4[0]; bfr[2 * p][1] = r4[1];
                bfr[2 * p + 1][0] = r4[2]; bfr[2 * p + 1][1] = r4[3];
            }
#pragma unroll
            for (int mi = 0; mi < 4; mi++)
#pragma unroll
                for (int ni = 0; ni < 8; ni++)
                    mma_bf16(acc[mi][ni], afr[mi], bfr[ni]);
        }
    }

    // ---- epilogue: out = acc * (A_SCALE*W_SCALE) + bias, FP32 ----
    const float SCALE = 5.0e-4f;
#pragma unroll
    for (int mi = 0; mi < 4; mi++) {
        const int row = m0 + wm + mi * 16 + g;
        float* p0 = out + (size_t)row * NDIM + n0 + wn;
        float* p1 = p0 + (size_t)8 * NDIM;
#pragma unroll
        for (int ni = 0; ni < 8; ni++) {
            const float* cc = acc[mi][ni];
            const int coff = ni * 8 + t * 2;
            float b0 = bias[n0 + wn + coff];
            float b1 = bias[n0 + wn + coff + 1];
            float2 v01, v23;
            v01.x = __fadd_rn(__fmul_rn(cc[0], SCALE), b0);
            v01.y = __fadd_rn(__fmul_rn(cc[1], SCALE), b1);
            v23.x = __fadd_rn(__fmul_rn(cc[2], SCALE), b0);
            v23.y = __fadd_rn(__fmul_rn(cc[3], SCALE), b1);
            *(float2*)(p0 + coff) = v01;
            *(float2*)(p1 + coff) = v23;
        }
    }
}

// ===================== launch =====================
extern "C" void kernel_launch(void* const* d_in, const int* in_sizes, int n_in,
                              void* d_out, int out_size) {
    const float* x    = nullptr;
    const int*   wp   = nullptr;
    const float* bias = nullptr;
    for (int i = 0; i < n_in; i++) {
        if (in_sizes[i] == MROWS * KDIM)            x    = (const float*)d_in[i];
        else if (in_sizes[i] == NDIM * KDIM / 2)    wp   = (const int*)d_in[i];
        else if (in_sizes[i] == NDIM)               bias = (const float*)d_in[i];
    }
    if (x == nullptr)    x    = (const float*)d_in[0];
    if (wp == nullptr)   wp   = (const int*)d_in[1];
    if (bias == nullptr) bias = (const float*)d_in[2];
    float* out = (float*)d_out;

    quant_kernel<<<(MROWS * KDIM / 16 + 255) / 256, 256>>>(x);
    unpack_kernel<<<(NDIM * KDIM / 8 + 255) / 256, 256>>>((const int4*)wp);

    cudaFuncSetAttribute(gemm_hmma, cudaFuncAttributeMaxDynamicSharedMemorySize, SMEM_BYTES);
    dim3 grid(NDIM / BN, MROWS / BM);   // (8, 256)
    gemm_hmma<<<grid, 128, SMEM_BYTES>>>(bias, out);
}

// round 17
// speedup vs baseline: 1.1006x; 1.0013x over previous
#include <cuda_runtime.h>
#include <cuda_bf16.h>
#include <cstdint>

// ===================== problem constants =====================
static constexpr int MROWS = 32768;
static constexpr int KDIM  = 1024;
static constexpr int NDIM  = 1024;

// ===================== HMMA GEMM tiling =====================
static constexpr int BM = 128;
static constexpr int BN = 128;
static constexpr int BK = 64;                 // bf16 k per tile (128 bytes)
static constexpr int KTILES = KDIM / BK;      // 16
static constexpr int NSTAGE = 3;
static constexpr int ROWB = 128;              // bytes per smem row (swizzled)
static constexpr int A_TILE = BM * ROWB;                // 16KB
static constexpr int B_TILE = BN * ROWB;                // 16KB
static constexpr int STAGE_BYTES = A_TILE + B_TILE;     // 32KB
static constexpr int SMEM_BYTES = NSTAGE * STAGE_BYTES; // 98304

// ===================== scratch =====================
__device__ __align__(16) __nv_bfloat16 g_qh[(size_t)MROWS * KDIM];   // bf16 acts (64MB)
__device__ __align__(16) __nv_bfloat16 g_wh[(size_t)NDIM * KDIM];    // bf16 weights (2MB)

// ===================== helpers =====================
__device__ __forceinline__ uint32_t smem_u32(const void* p) {
    uint32_t a;
    asm("{ .reg .u64 t; cvta.to.shared.u64 t, %1; cvt.u32.u64 %0, t; }" : "=r"(a) : "l"(p));
    return a;
}
__device__ __forceinline__ void cp_async16(uint32_t dst, const void* src) {
    asm volatile("cp.async.cg.shared.global [%0], [%1], 16;" :: "r"(dst), "l"(src) : "memory");
}
__device__ __forceinline__ void cp_commit() {
    asm volatile("cp.async.commit_group;" ::: "memory");
}
template <int N>
__device__ __forceinline__ void cp_wait() {
    asm volatile("cp.async.wait_group %0;" :: "n"(N) : "memory");
}
__device__ __forceinline__ void ldsm_x4(uint32_t* r, uint32_t addr) {
    asm volatile("ldmatrix.sync.aligned.m8n8.x4.shared.b16 {%0,%1,%2,%3}, [%4];"
                 : "=r"(r[0]), "=r"(r[1]), "=r"(r[2]), "=r"(r[3]) : "r"(addr));
}
__device__ __forceinline__ void mma_bf16(float* d, const uint32_t* a, const uint32_t* b) {
    asm volatile(
        "mma.sync.aligned.m16n8k16.row.col.f32.bf16.bf16.f32 "
        "{%0,%1,%2,%3}, {%4,%5,%6,%7}, {%8,%9}, {%0,%1,%2,%3};"
        : "+f"(d[0]), "+f"(d[1]), "+f"(d[2]), "+f"(d[3])
        : "r"(a[0]), "r"(a[1]), "r"(a[2]), "r"(a[3]), "r"(b[0]), "r"(b[1]));
}

// ===================== pass 1: quantize fp32 -> bf16 ints =====================
__global__ void __launch_bounds__(256) quant_kernel(const float* __restrict__ x) {
    const int i = blockIdx.x * blockDim.x + threadIdx.x;   // one 16-element group
    const int ngroups = (MROWS * KDIM) / 16;
    if (i >= ngroups) return;
    const float4* xv = (const float4*)x + i * 4;
    uint32_t hb[8];
#pragma unroll
    for (int j = 0; j < 4; j++) {
        float4 v = xv[j];
        int q0 = max(-127, min(127, __float2int_rn(__fmul_rn(v.x, 20.0f))));
        int q1 = max(-127, min(127, __float2int_rn(__fmul_rn(v.y, 20.0f))));
        int q2 = max(-127, min(127, __float2int_rn(__fmul_rn(v.z, 20.0f))));
        int q3 = max(-127, min(127, __float2int_rn(__fmul_rn(v.w, 20.0f))));
        __nv_bfloat162 p01 = __floats2bfloat162_rn((float)q0, (float)q1);
        __nv_bfloat162 p23 = __floats2bfloat162_rn((float)q2, (float)q3);
        hb[2 * j]     = *(uint32_t*)&p01;
        hb[2 * j + 1] = *(uint32_t*)&p23;
    }
    uint4 h0; h0.x = hb[0]; h0.y = hb[1]; h0.z = hb[2]; h0.w = hb[3];
    uint4 h1; h1.x = hb[4]; h1.y = hb[5]; h1.z = hb[6]; h1.w = hb[7];
    ((uint4*)g_qh)[i * 2]     = h0;
    ((uint4*)g_qh)[i * 2 + 1] = h1;
}

// ===================== pass 1b: unpack int4 -> bf16 =====================
// weight_packed delivered as int32 elements (uint8 widened by harness).
__global__ void __launch_bounds__(256) unpack_kernel(const int4* __restrict__ wp) {
    int i = blockIdx.x * blockDim.x + threadIdx.x;   // one int4 = 4 packed bytes = 8 weights
    if (i >= (NDIM * KDIM) / 8) return;
    int4 e = wp[i];
    int b[4] = {e.x & 0xFF, e.y & 0xFF, e.z & 0xFF, e.w & 0xFF};
    uint4 h;
    uint32_t* hw = (uint32_t*)&h;
#pragma unroll
    for (int j = 0; j < 4; j++) {
        int lo = (b[j] & 0xF);        lo -= (lo >= 8) ? 16 : 0;
        int hi = (b[j] >> 4) & 0xF;   hi -= (hi >= 8) ? 16 : 0;
        __nv_bfloat162 p = __floats2bfloat162_rn((float)lo, (float)hi);
        hw[j] = *(uint32_t*)&p;
    }
    ((uint4*)g_wh)[i] = h;
}

// ===================== pass 2: HMMA bf16 GEMM, double-buffered fragments =====================
// CTA: 128 threads = 4 warps in 2(m) x 2(n); warp tile 64x64 (mi=4, ni=8).
__global__ void __launch_bounds__(128, 2)
gemm_hmma(const float* __restrict__ bias, float* __restrict__ out) {
    extern __shared__ char smem[];
    const uint32_t sbase = smem_u32(smem);
    const int tid  = threadIdx.x;
    const int wid  = tid >> 5;
    const int lane = tid & 31;
    const int g = lane >> 2, t = lane & 3;
    const int wm = (wid & 1) * 64;
    const int wn = (wid >> 1) * 64;
    const int n0 = blockIdx.x * BN;
    const int m0 = blockIdx.y * BM;

    const __nv_bfloat16* gA = g_qh + (size_t)m0 * KDIM;
    const __nv_bfloat16* gB = g_wh + (size_t)n0 * KDIM;

    // swizzled store: row r, 16B-chunk c -> offset r*128 + (c ^ (r&7))*16
    auto load_stage = [&](int s, int kt) {
        const uint32_t sa = sbase + s * STAGE_BYTES;
        const uint32_t sb = sa + A_TILE;
        const int kb = kt * BK;       // bf16 elements
#pragma unroll
        for (int it = 0; it < 8; it++) {
            int c = tid + it * 128;           // 1024 chunks for A (128 rows x 8)
            int row = c >> 3, col = c & 7;
            int scol = col ^ (row & 7);
            cp_async16(sa + row * ROWB + scol * 16,
                       gA + (size_t)row * KDIM + kb + col * 8);
        }
#pragma unroll
        for (int it = 0; it < 8; it++) {
            int c = tid + it * 128;           // 1024 chunks for B (128 rows x 8)
            int row = c >> 3, col = c & 7;
            int scol = col ^ (row & 7);
            cp_async16(sb + row * ROWB + scol * 16,
                       gB + (size_t)row * KDIM + kb + col * 8);
        }
    };

    float acc[4][8][4];
#pragma unroll
    for (int mi = 0; mi < 4; mi++)
#pragma unroll
        for (int ni = 0; ni < 8; ni++)
#pragma unroll
            for (int r = 0; r < 4; r++) acc[mi][ni][r] = 0.0f;

    const int a_row   = wm + (lane & 15);
    const int a_chunk = lane >> 4;                              // 0 or 1
    const int b_row   = wn + (lane & 7) + ((lane >> 4) << 3);
    const int b_chunk = (lane >> 3) & 1;                        // 0 or 1

    // double-buffered fragments
    uint32_t afr[2][4][4];
    uint32_t bfr[2][8][2];

    // fragment loader for k16 chunk c of stage (sa, sb) into buffer buf
    auto load_frags = [&](uint32_t sa, uint32_t sb, int c, int buf) {
#pragma unroll
        for (int mi = 0; mi < 4; mi++) {
            int r = a_row + mi * 16;
            int ch = (2 * c + a_chunk) ^ (r & 7);
            ldsm_x4(afr[buf][mi], sa + r * ROWB + ch * 16);
        }
#pragma unroll
        for (int p = 0; p < 4; p++) {
            int r = b_row + p * 16;
            int ch = (2 * c + b_chunk) ^ (r & 7);
            uint32_t r4[4];
            ldsm_x4(r4, sb + r * ROWB + ch * 16);
            bfr[buf][2 * p][0] = r4[0]; bfr[buf][2 * p][1] = r4[1];
            bfr[buf][2 * p + 1][0] = r4[2]; bfr[buf][2 * p + 1][1] = r4[3];
        }
    };

    // prologue: stages 0 and 1 (one commit group each)
    load_stage(0, 0); cp_commit();
    load_stage(1, 1); cp_commit();

#pragma unroll 1
    for (int kt = 0; kt < KTILES; kt++) {
        cp_wait<1>();        // stage kt's group complete (exactly 1 newer group)
        __syncthreads();     // arrival visible + stage (kt-1) reads done before overwrite
        if (kt + 2 < KTILES) load_stage((kt + 2) % NSTAGE, kt + 2);
        cp_commit();         // unconditional: keeps group algebra uniform

        const uint32_t sa = sbase + (kt % NSTAGE) * STAGE_BYTES;
        const uint32_t sb = sa + A_TILE;

        load_frags(sa, sb, 0, 0);
#pragma unroll
        for (int c = 0; c < 4; c++) {                 // four k16 chunks per ktile
            const int cur = c & 1;
            if (c < 3) load_frags(sa, sb, c + 1, cur ^ 1);   // prefetch next chunk's frags
#pragma unroll
            for (int mi = 0; mi < 4; mi++)
#pragma unroll
                for (int ni = 0; ni < 8; ni++)
                    mma_bf16(acc[mi][ni], afr[cur][mi], bfr[cur][ni]);
        }
    }

    // ---- epilogue: out = acc * (A_SCALE*W_SCALE) + bias, FP32 ----
    const float SCALE = 5.0e-4f;
#pragma unroll
    for (int mi = 0; mi < 4; mi++) {
        const int row = m0 + wm + mi * 16 + g;
        float* p0 = out + (size_t)row * NDIM + n0 + wn;
        float* p1 = p0 + (size_t)8 * NDIM;
#pragma unroll
        for (int ni = 0; ni < 8; ni++) {
            const float* cc = acc[mi][ni];
            const int coff = ni * 8 + t * 2;
            float b0 = bias[n0 + wn + coff];
            float b1 = bias[n0 + wn + coff + 1];
            float2 v01, v23;
            v01.x = __fadd_rn(__fmul_rn(cc[0], SCALE), b0);
            v01.y = __fadd_rn(__fmul_rn(cc[1], SCALE), b1);
            v23.x = __fadd_rn(__fmul_rn(cc[2], SCALE), b0);
            v23.y = __fadd_rn(__fmul_rn(cc[3], SCALE), b1);
            *(float2*)(p0 + coff) = v01;
            *(float2*)(p1 + coff) = v23;
        }
    }
}

// ===================== launch =====================
extern "C" void kernel_launch(void* const* d_in, const int* in_sizes, int n_in,
                              void* d_out, int out_size) {
    const float* x    = nullptr;
    const int*   wp   = nullptr;
    const float* bias = nullptr;
    for (int i = 0; i < n_in; i++) {
        if (in_sizes[i] == MROWS * KDIM)            x    = (const float*)d_in[i];
        else if (in_sizes[i] == NDIM * KDIM / 2)    wp   = (const int*)d_in[i];
        else if (in_sizes[i] == NDIM)               bias = (const float*)d_in[i];
    }
    if (x == nullptr)    x    = (const float*)d_in[0];
    if (wp == nullptr)   wp   = (const int*)d_in[1];
    if (bias == nullptr) bias = (const float*)d_in[2];
    float* out = (float*)d_out;

    quant_kernel<<<(MROWS * KDIM / 16 + 255) / 256, 256>>>(x);
    unpack_kernel<<<(NDIM * KDIM / 8 + 255) / 256, 256>>>((const int4*)wp);

    cudaFuncSetAttribute(gemm_hmma, cudaFuncAttributeMaxDynamicSharedMemorySize, SMEM_BYTES);
    dim3 grid(NDIM / BN, MROWS / BM);   // (8, 256)
    gemm_hmma<<<grid, 128, SMEM_BYTES>>>(bias, out);
}